// round 11
// baseline (speedup 1.0000x reference)
#include <cuda_runtime.h>
#include <cstdint>

// Fixed shapes per reference: B=256, L=512, N=50000
constexpr int B_SZ   = 256;
constexpr int L_SEQ  = 512;
constexpr int N_LOC  = 50000;
constexpr int HSIZE  = 1024;               // hash slots (pow2), load factor 0.5
constexpr int NT     = 256;
constexpr int SEGS   = 4;                  // CTAs per row (grid = 1024, single wave)
constexpr int ROW_F4 = N_LOC / 4;          // 12,500 float4 per row
constexpr int CHUNK_F4 = ROW_F4 / SEGS;    // 3,125 float4 (50 KB) per CTA
constexpr int CAP    = 512;                // max distinct keys per row
constexpr int PAD    = 32;                 // 128B padding between row counters

__device__ int   g_done[B_SZ * PAD];       // zero-initialized at module load
__device__ int   g_n  [B_SZ];
__device__ int   g_key[B_SZ * CAP];
__device__ float g_val[B_SZ * CAP];

__global__ __launch_bounds__(NT, 8)
void fused_kernel(const int* __restrict__ loc_seq,
                  const int* __restrict__ mask,
                  const float* __restrict__ rw_p,
                  const float* __restrict__ fw_p,
                  float* __restrict__ out)
{
    const int b   = blockIdx.x >> 2;       // row
    const int q   = blockIdx.x & 3;        // quarter within row
    const int tid = threadIdx.x;

    __shared__ int      h_key[HSIZE];
    __shared__ int      h_cnt[HSIZE];
    __shared__ unsigned h_rec[HSIZE];      // float bits; all values >= 0
    __shared__ int      s_maxcnt;
    __shared__ int      s_n;
    __shared__ int      s_skey[CAP];
    __shared__ float    s_sval[CAP];
    __shared__ int      s_last;

    float* const row = out + (size_t)b * N_LOC;

    if (q == 0) {
        // ---------------- builder quarter ----------------
        #pragma unroll 4
        for (int i = tid; i < HSIZE; i += NT) {
            h_key[i] = -1;
            h_cnt[i] = 0;
            h_rec[i] = 0u;
        }
        if (tid == 0) { s_maxcnt = 0; s_n = 0; }
        __syncthreads();

        // zero own quarter (LSU) — overlaps with the smem hash work below
        {
            float4* row4 = reinterpret_cast<float4*>(row);
            const float4 z = make_float4(0.f, 0.f, 0.f, 0.f);
            #pragma unroll 4
            for (int i = tid; i < CHUNK_F4; i += NT)
                row4[i] = z;
        }

        const float l2rw = log2f(*rw_p);
        const int2* lrow = reinterpret_cast<const int2*>(loc_seq + (size_t)b * L_SEQ);
        const int2* mrow = reinterpret_cast<const int2*>(mask    + (size_t)b * L_SEQ);
        const int2 lk = lrow[tid];
        const int2 mk = mrow[tid];

        #pragma unroll
        for (int j = 0; j < 2; j++) {
            const int t   = 2 * tid + j;
            const int key = (j == 0) ? lk.x : lk.y;
            const int m   = (j == 0) ? mk.x : mk.y;
            const float rec = m ? exp2f((float)(L_SEQ - 1 - t) * l2rw) : 0.0f;

            unsigned h = ((unsigned)key * 2654435761u) & (HSIZE - 1);
            for (;;) {
                int cur = h_key[h];
                if (cur == key) break;
                if (cur == -1) {
                    int prev = atomicCAS(&h_key[h], -1, key);
                    if (prev == -1 || prev == key) break;
                }
                h = (h + 1) & (HSIZE - 1);
            }
            atomicAdd(&h_cnt[h], m);
            atomicMax(&h_rec[h], __float_as_uint(rec));
        }
        __syncthreads();

        int mf = 0;
        #pragma unroll 4
        for (int i = tid; i < HSIZE; i += NT) mf = max(mf, h_cnt[i]);
        #pragma unroll
        for (int o = 16; o > 0; o >>= 1) mf = max(mf, __shfl_xor_sync(0xFFFFFFFFu, mf, o));
        if ((tid & 31) == 0) atomicMax(&s_maxcnt, mf);
        __syncthreads();

        const float inv = (*fw_p) / fmaxf((float)s_maxcnt, 1.0f);

        // compact final values: smem list + global scratch (for a non-builder last finisher)
        #pragma unroll 4
        for (int i = tid; i < HSIZE; i += NT) {
            const int key = h_key[i];
            if (key >= 0) {
                const float val = __uint_as_float(h_rec[i]) + (float)h_cnt[i] * inv;
                const int pos = atomicAdd(&s_n, 1);
                s_skey[pos] = key;
                s_sval[pos] = val;
                g_key[b * CAP + pos] = key;
                g_val[b * CAP + pos] = val;
            }
        }
        __syncthreads();
        if (tid == 0) g_n[b] = s_n;

        __threadfence();                   // release: zeros + scratch visible
        __syncthreads();
        if (tid == 0) {
            const int old = atomicAdd(&g_done[b * PAD], 1);
            s_last = (old == SEGS - 1);
            if (s_last) g_done[b * PAD] = 0;   // unique last finisher resets (replay-safe)
        }
        __syncthreads();

        if (s_last) {
            __threadfence();               // acquire: siblings' zero stores visible
            const int n = s_n;             // scatter straight from smem
            for (int i = tid; i < n; i += NT)
                row[s_skey[i]] = s_sval[i];
        }
        return;
    }

    // ---------------- sibling quarter ----------------
    {
        float4* row4 = reinterpret_cast<float4*>(row);
        const float4 z = make_float4(0.f, 0.f, 0.f, 0.f);
        const int i0 = q * CHUNK_F4;
        #pragma unroll 4
        for (int i = i0 + tid; i < i0 + CHUNK_F4; i += NT)
            row4[i] = z;
    }
    __threadfence();                       // release my zero stores
    __syncthreads();
    if (tid == 0) {
        const int old = atomicAdd(&g_done[b * PAD], 1);
        s_last = (old == SEGS - 1);
        if (s_last) g_done[b * PAD] = 0;
    }
    __syncthreads();

    if (s_last) {
        __threadfence();                   // acquire: builder's scratch + all zeros
        const int n = g_n[b];
        for (int i = tid; i < n; i += NT)
            row[g_key[b * CAP + i]] = g_val[b * CAP + i];
    }
}

extern "C" void kernel_launch(void* const* d_in, const int* in_sizes, int n_in,
                              void* d_out, int out_size)
{
    const int*   loc_seq = (const int*)  d_in[0];   // (B, L) int32
    const int*   mask    = (const int*)  d_in[1];   // (B, L) int32
    const float* rw      = (const float*)d_in[2];   // scalar
    const float* fw      = (const float*)d_in[3];   // scalar
    float*       out     = (float*)d_out;           // (B, N) float32

    fused_kernel<<<B_SZ * SEGS, NT>>>(loc_seq, mask, rw, fw, out);
}

// round 12
// speedup vs baseline: 1.0046x; 1.0046x over previous
#include <cuda_runtime.h>
#include <cstdint>

// Fixed shapes per reference: B=256, L=512, N=50000
constexpr int B_SZ   = 256;
constexpr int L_SEQ  = 512;
constexpr int N_LOC  = 50000;
constexpr int HSIZE  = 1024;                 // hash slots (pow2), load factor 0.5
constexpr int NT     = 512;
constexpr int ROW_BYTES  = N_LOC * 4;        // 200,000 (multiple of 16)
constexpr int N_COPIES   = 4;
constexpr int COPY_BYTES = ROW_BYTES / N_COPIES;  // 50,000 (multiple of 16)

// Dynamic smem layout: [h_key 4K][h_cnt 4K][h_rec 4K][row image 200,000]
constexpr int SM_HKEY = 0;
constexpr int SM_HCNT = 4096;
constexpr int SM_HREC = 8192;
constexpr int SM_IMG  = 12288;
constexpr int SMEM_TOTAL = SM_IMG + ROW_BYTES;    // 212,288 bytes

__device__ __forceinline__ uint32_t smem_u32(const void* p) {
    uint32_t a;
    asm("{ .reg .u64 t; cvta.to.shared.u64 t, %1; cvt.u32.u64 %0, t; }" : "=r"(a) : "l"(p));
    return a;
}

__global__ __launch_bounds__(NT, 1)
void fused_kernel(const int* __restrict__ loc_seq,
                  const int* __restrict__ mask,
                  const float* __restrict__ rw_p,
                  const float* __restrict__ fw_p,
                  float* __restrict__ out)
{
    extern __shared__ char smem[];
    int*      h_key = reinterpret_cast<int*>     (smem + SM_HKEY);
    int*      h_cnt = reinterpret_cast<int*>     (smem + SM_HCNT);
    unsigned* h_rec = reinterpret_cast<unsigned*>(smem + SM_HREC);
    float*    img   = reinterpret_cast<float*>   (smem + SM_IMG);
    __shared__ int s_maxcnt;

    const int b   = blockIdx.x;              // one CTA per batch row
    const int tid = threadIdx.x;

    // ---- init hash + zero the 200 KB row image (smem bandwidth, ~0.9 us) ----
    #pragma unroll
    for (int i = tid; i < HSIZE; i += NT) {
        h_key[i] = -1;
        h_cnt[i] = 0;
        h_rec[i] = 0u;
    }
    if (tid == 0) s_maxcnt = 0;
    {
        float4* img4 = reinterpret_cast<float4*>(img);
        const float4 z = make_float4(0.f, 0.f, 0.f, 0.f);
        #pragma unroll 4
        for (int i = tid; i < ROW_BYTES / 16; i += NT)
            img4[i] = z;
    }
    __syncthreads();

    // ---- build the row hash once (1 timestep per thread) ----
    const float l2rw = log2f(*rw_p);
    {
        const int t   = tid;
        const int key = loc_seq[(size_t)b * L_SEQ + t];
        const int m   = mask   [(size_t)b * L_SEQ + t];
        const float rec = m ? exp2f((float)(L_SEQ - 1 - t) * l2rw) : 0.0f;

        unsigned h = ((unsigned)key * 2654435761u) & (HSIZE - 1);
        for (;;) {
            int cur = h_key[h];
            if (cur == key) break;
            if (cur == -1) {
                int prev = atomicCAS(&h_key[h], -1, key);
                if (prev == -1 || prev == key) break;
            }
            h = (h + 1) & (HSIZE - 1);
        }
        atomicAdd(&h_cnt[h], m);
        atomicMax(&h_rec[h], __float_as_uint(rec));
    }
    __syncthreads();

    // ---- block reduce: max frequency count (2 slots per thread) ----
    int mf = max(h_cnt[tid], h_cnt[tid + NT]);
    #pragma unroll
    for (int o = 16; o > 0; o >>= 1) mf = max(mf, __shfl_xor_sync(0xFFFFFFFFu, mf, o));
    if ((tid & 31) == 0) atomicMax(&s_maxcnt, mf);
    __syncthreads();

    const float inv = (*fw_p) / fmaxf((float)s_maxcnt, 1.0f);

    // ---- scatter final values INTO the smem image (no global scatter pass) ----
    #pragma unroll
    for (int i = tid; i < HSIZE; i += NT) {
        const int key = h_key[i];
        if (key >= 0) {
            img[key] = __uint_as_float(h_rec[i]) + (float)h_cnt[i] * inv;
        }
    }
    __syncthreads();
    // order generic smem writes before async-proxy reads
    asm volatile("fence.proxy.async.shared::cta;" ::: "memory");

    // ---- stream the finished row to global: 4 x 50 KB bulk stores ----
    if (tid == 0) {
        char* dst = (char*)out + (size_t)b * ROW_BYTES;
        const uint32_t src = smem_u32(img);
        #pragma unroll
        for (int c = 0; c < N_COPIES; c++) {
            asm volatile(
                "cp.async.bulk.global.shared::cta.bulk_group [%0], [%1], %2;"
                :: "l"(dst + c * COPY_BYTES), "r"(src + c * COPY_BYTES), "r"(COPY_BYTES)
                : "memory");
        }
        asm volatile("cp.async.bulk.commit_group;" ::: "memory");
        asm volatile("cp.async.bulk.wait_group 0;" ::: "memory");
    }
    __syncthreads();   // keep smem alive until copies complete
}

extern "C" void kernel_launch(void* const* d_in, const int* in_sizes, int n_in,
                              void* d_out, int out_size)
{
    const int*   loc_seq = (const int*)  d_in[0];   // (B, L) int32
    const int*   mask    = (const int*)  d_in[1];   // (B, L) int32
    const float* rw      = (const float*)d_in[2];   // scalar
    const float* fw      = (const float*)d_in[3];   // scalar
    float*       out     = (float*)d_out;           // (B, N) float32

    cudaFuncSetAttribute(fused_kernel,
                         cudaFuncAttributeMaxDynamicSharedMemorySize, SMEM_TOTAL);
    fused_kernel<<<B_SZ, NT, SMEM_TOTAL>>>(loc_seq, mask, rw, fw, out);
}

// round 13
// speedup vs baseline: 1.2462x; 1.2405x over previous
#include <cuda_runtime.h>
#include <cstdint>

// Fixed shapes per reference: B=256, L=512, N=50000
constexpr int B_SZ   = 256;
constexpr int L_SEQ  = 512;
constexpr int N_LOC  = 50000;
constexpr int HSIZE  = 1024;              // hash slots (pow2), load factor 0.5
constexpr int NT     = 512;
constexpr int SEGS   = 2;                 // CTAs per row (grid = 512, one wave)
constexpr int HALF_ELEMS = N_LOC / SEGS;  // 25,000 floats
constexpr int HALF_F4    = HALF_ELEMS / 4; // 6,250 float4 per CTA

__global__ __launch_bounds__(NT, 4)
void fused_kernel(const int* __restrict__ loc_seq,
                  const int* __restrict__ mask,
                  const float* __restrict__ rw_p,
                  const float* __restrict__ fw_p,
                  float* __restrict__ out)
{
    const int b    = blockIdx.x >> 1;     // batch row
    const int half = blockIdx.x & 1;      // which half of the row this CTA owns
    const int tid  = threadIdx.x;

    __shared__ int      h_key[HSIZE];
    __shared__ int      h_cnt[HSIZE];
    __shared__ unsigned h_rec[HSIZE];     // float bits; all values >= 0
    __shared__ int      s_maxcnt;

    // ---- init hash (2 slots per thread) ----
    h_key[tid]        = -1;
    h_key[tid + NT]   = -1;
    h_cnt[tid]        = 0;
    h_cnt[tid + NT]   = 0;
    h_rec[tid]        = 0u;
    h_rec[tid + NT]   = 0u;
    if (tid == 0) s_maxcnt = 0;

    // ---- zero own half-row: the long pole; issue all stores first ----
    float* const row = out + (size_t)b * N_LOC;
    {
        float4* half4 = reinterpret_cast<float4*>(row + half * HALF_ELEMS);
        const float4 z = make_float4(0.f, 0.f, 0.f, 0.f);
        #pragma unroll 4
        for (int i = tid; i < HALF_F4; i += NT)
            half4[i] = z;
    }
    __syncthreads();   // hash init complete (also fences the zero stores, cta scope)

    // ---- build the FULL row hash (1 timestep per thread; 2x redundancy per row) ----
    const float l2rw = log2f(*rw_p);
    {
        const int t   = tid;
        const int key = loc_seq[(size_t)b * L_SEQ + t];
        const int m   = mask   [(size_t)b * L_SEQ + t];
        const float rec = m ? exp2f((float)(L_SEQ - 1 - t) * l2rw) : 0.0f;

        unsigned h = ((unsigned)key * 2654435761u) & (HSIZE - 1);
        for (;;) {
            int cur = h_key[h];
            if (cur == key) break;
            if (cur == -1) {
                int prev = atomicCAS(&h_key[h], -1, key);
                if (prev == -1 || prev == key) break;
            }
            h = (h + 1) & (HSIZE - 1);
        }
        atomicAdd(&h_cnt[h], m);
        atomicMax(&h_rec[h], __float_as_uint(rec));
    }
    __syncthreads();

    // ---- block reduce: max frequency count (2 slots per thread) ----
    int mf = max(h_cnt[tid], h_cnt[tid + NT]);
    #pragma unroll
    for (int o = 16; o > 0; o >>= 1) mf = max(mf, __shfl_xor_sync(0xFFFFFFFFu, mf, o));
    if ((tid & 31) == 0) atomicMax(&s_maxcnt, mf);
    __syncthreads();   // s_maxcnt final; fences zero stores before scatter stores

    const float inv = (*fw_p) / fmaxf((float)s_maxcnt, 1.0f);

    // ---- scatter final values for keys in THIS CTA's half (local ordering only) ----
    const int lo = half * HALF_ELEMS;
    const int hi = lo + HALF_ELEMS;
    #pragma unroll
    for (int i = tid; i < HSIZE; i += NT) {
        const int key = h_key[i];
        if (key >= lo && key < hi) {
            row[key] = __uint_as_float(h_rec[i]) + (float)h_cnt[i] * inv;
        }
    }
}

extern "C" void kernel_launch(void* const* d_in, const int* in_sizes, int n_in,
                              void* d_out, int out_size)
{
    const int*   loc_seq = (const int*)  d_in[0];   // (B, L) int32
    const int*   mask    = (const int*)  d_in[1];   // (B, L) int32
    const float* rw      = (const float*)d_in[2];   // scalar
    const float* fw      = (const float*)d_in[3];   // scalar
    float*       out     = (float*)d_out;           // (B, N) float32

    fused_kernel<<<B_SZ * SEGS, NT>>>(loc_seq, mask, rw, fw, out);
}